// round 1
// baseline (speedup 1.0000x reference)
#include <cuda_runtime.h>
#include <math.h>

// Problem constants
constexpr int NB   = 1024;   // batch
constexpr int NH   = 1024;   // rnn size
constexpr int NI   = 69;     // input size
constexpr int NSRC = 50;
constexpr int NDEC = 24;     // TGT-1
constexpr int NT   = 74;     // total frames
constexpr int H3   = 3 * NH; // 3072

// Scratch (device globals: allocation-free rule)
__device__ float g_h[NB * NH];          // hidden state (updated in place)
__device__ float g_gh[NB * H3];         // h @ w_hh^T
__device__ float g_gi[NB * H3];         // x @ w_ih^T + b_ih
__device__ float g_out[NT * NB * NI];   // decode outputs [t][b][i]
__device__ float g_part[8 * NB * NI];   // split-K partials for fc1

// x source: kind 0 -> frame t (from enc/dec), kind 1 -> g_out row t
__device__ __forceinline__ const float* x_base(int kind, int t,
                                               const float* enc, const float* dec,
                                               int* stride) {
    if (kind == 0) {
        if (t < NSRC) { *stride = NSRC * NI; return enc + t * NI; }
        *stride = NDEC * NI; return dec + (t - NSRC) * NI;
    }
    *stride = NI;
    return g_out + (size_t)t * NB * NI;
}

__global__ void k_zero() {
    int i = blockIdx.x * blockDim.x + threadIdx.x;
    if (i < NB * NH) g_h[i] = 0.0f;
}

// g_gi[m][n] = b_ih[n] + sum_{k<69} x[m][k] * w_ih[n][k]
// grid (48, 16), 256 threads, 64x64 tile, 4x4 micro
__global__ void k_gi(const float* __restrict__ enc, const float* __restrict__ dec,
                     const float* __restrict__ w_ih, const float* __restrict__ b_ih,
                     int kind, int t) {
    __shared__ float Xs[NI][65];   // [k][m], pad -> conflict-free
    __shared__ float Ws[NI][65];

    int stride;
    const float* x = x_base(kind, t, enc, dec, &stride);

    const int m0 = blockIdx.y * 64;
    const int n0 = blockIdx.x * 64;
    const int tid = threadIdx.x;

    const float* wbase = w_ih + (size_t)n0 * NI;  // rows n0..n0+63 contiguous
    for (int idx = tid; idx < 64 * NI; idx += 256) {
        int m = idx / NI;
        int k = idx - m * NI;
        Xs[k][m] = x[(size_t)(m0 + m) * stride + k];
        Ws[k][m] = wbase[idx];
    }
    __syncthreads();

    const int tx = tid & 15, ty = tid >> 4;
    float acc[4][4] = {};
    #pragma unroll 3
    for (int k = 0; k < NI; k++) {
        float a[4], bb[4];
        #pragma unroll
        for (int i = 0; i < 4; i++) a[i] = Xs[k][ty * 4 + i];
        #pragma unroll
        for (int j = 0; j < 4; j++) bb[j] = Ws[k][tx * 4 + j];
        #pragma unroll
        for (int i = 0; i < 4; i++)
            #pragma unroll
            for (int j = 0; j < 4; j++)
                acc[i][j] += a[i] * bb[j];
    }

    #pragma unroll
    for (int i = 0; i < 4; i++) {
        int m = m0 + ty * 4 + i;
        #pragma unroll
        for (int j = 0; j < 4; j++) {
            int n = n0 + tx * 4 + j;
            g_gi[(size_t)m * H3 + n] = acc[i][j] + b_ih[n];
        }
    }
}

// g_gh[m][n] = sum_{k<1024} g_h[m][k] * w_hh[n][k]
// grid (48, 16), 256 threads, 64x64x32 tiles, 4x4 micro, float4 loads
__global__ void k_gh(const float* __restrict__ whh) {
    __shared__ float As[32][68];   // [k][m], row = 272B (16B aligned)
    __shared__ float Bs[32][68];

    const int m0 = blockIdx.y * 64;
    const int n0 = blockIdx.x * 64;
    const int tid = threadIdx.x;
    const int tx = tid & 15, ty = tid >> 4;

    float acc[4][4] = {};

    for (int k0 = 0; k0 < NH; k0 += 32) {
        #pragma unroll
        for (int u = 0; u < 2; u++) {
            int idx = tid + u * 256;            // 0..511
            int m = idx >> 3;                   // 64 rows
            int kq = (idx & 7) * 4;             // 8 float4 per row
            float4 va = *(const float4*)(g_h + (size_t)(m0 + m) * NH + k0 + kq);
            As[kq + 0][m] = va.x; As[kq + 1][m] = va.y;
            As[kq + 2][m] = va.z; As[kq + 3][m] = va.w;
            float4 vb = *(const float4*)(whh + (size_t)(n0 + m) * NH + k0 + kq);
            Bs[kq + 0][m] = vb.x; Bs[kq + 1][m] = vb.y;
            Bs[kq + 2][m] = vb.z; Bs[kq + 3][m] = vb.w;
        }
        __syncthreads();

        #pragma unroll
        for (int k = 0; k < 32; k++) {
            float4 a4 = *(const float4*)&As[k][ty * 4];
            float4 b4 = *(const float4*)&Bs[k][tx * 4];
            float a[4] = {a4.x, a4.y, a4.z, a4.w};
            float bb[4] = {b4.x, b4.y, b4.z, b4.w};
            #pragma unroll
            for (int i = 0; i < 4; i++)
                #pragma unroll
                for (int j = 0; j < 4; j++)
                    acc[i][j] += a[i] * bb[j];
        }
        __syncthreads();
    }

    #pragma unroll
    for (int i = 0; i < 4; i++) {
        int m = m0 + ty * 4 + i;
        #pragma unroll
        for (int j = 0; j < 4; j++) {
            int n = n0 + tx * 4 + j;
            g_gh[(size_t)m * H3 + n] = acc[i][j];
        }
    }
}

// GRU gate combine, in-place h update
__global__ void k_combine(const float* __restrict__ b_hh) {
    int idx = blockIdx.x * blockDim.x + threadIdx.x;
    if (idx >= NB * NH) return;
    int b = idx >> 10;
    int j = idx & (NH - 1);
    size_t base = (size_t)b * H3 + j;

    float ir  = g_gi[base];
    float iz  = g_gi[base + NH];
    float inn = g_gi[base + 2 * NH];
    float hr  = g_gh[base]          + b_hh[j];
    float hz  = g_gh[base + NH]     + b_hh[NH + j];
    float hn  = g_gh[base + 2 * NH] + b_hh[2 * NH + j];

    float r = 1.0f / (1.0f + expf(-(ir + hr)));
    float z = 1.0f / (1.0f + expf(-(iz + hz)));
    float n = tanhf(inn + r * hn);
    g_h[idx] = (1.0f - z) * n + z * g_h[idx];
}

// split-K partials for out = h @ fc1_w^T : grid (16 m-blocks, 8 k-splits)
__global__ void k_out(const float* __restrict__ fc1w) {
    __shared__ float As[32][68];
    __shared__ float Bs[32][80];   // n padded to 80, zero-filled

    const int m0 = blockIdx.x * 64;
    const int ks = blockIdx.y;          // 0..7, K-chunk of 128
    const int tid = threadIdx.x;
    const int tx = tid & 15, ty = tid >> 4;

    float acc[4][5] = {};

    for (int kt = 0; kt < 4; kt++) {
        int k0 = ks * 128 + kt * 32;
        #pragma unroll
        for (int u = 0; u < 2; u++) {
            int idx = tid + u * 256;
            int m = idx >> 3;
            int kq = (idx & 7) * 4;
            float4 va = *(const float4*)(g_h + (size_t)(m0 + m) * NH + k0 + kq);
            As[kq + 0][m] = va.x; As[kq + 1][m] = va.y;
            As[kq + 2][m] = va.z; As[kq + 3][m] = va.w;
        }
        for (int idx = tid; idx < 80 * 32; idx += 256) {
            int n = idx >> 5;
            int k = idx & 31;
            Bs[k][n] = (n < NI) ? fc1w[(size_t)n * NH + k0 + k] : 0.0f;
        }
        __syncthreads();

        #pragma unroll
        for (int k = 0; k < 32; k++) {
            float4 a4 = *(const float4*)&As[k][ty * 4];
            float a[4] = {a4.x, a4.y, a4.z, a4.w};
            float bb[5];
            #pragma unroll
            for (int j = 0; j < 5; j++) bb[j] = Bs[k][tx * 5 + j];
            #pragma unroll
            for (int i = 0; i < 4; i++)
                #pragma unroll
                for (int j = 0; j < 5; j++)
                    acc[i][j] += a[i] * bb[j];
        }
        __syncthreads();
    }

    #pragma unroll
    for (int i = 0; i < 4; i++) {
        int m = m0 + ty * 4 + i;
        #pragma unroll
        for (int j = 0; j < 5; j++) {
            int n = tx * 5 + j;
            if (n < NI)
                g_part[(size_t)ks * NB * NI + (size_t)m * NI + n] = acc[i][j];
        }
    }
}

// out[t][b][i] = x[b][i] + fc1_b[i] + sum_p part[p][b][i]
__global__ void k_outred(const float* __restrict__ enc, const float* __restrict__ dec,
                         const float* __restrict__ fc1b, int xkind, int xt, int t) {
    int idx = blockIdx.x * blockDim.x + threadIdx.x;
    if (idx >= NB * NI) return;
    int b = idx / NI;
    int i = idx - b * NI;
    int stride;
    const float* x = x_base(xkind, xt, enc, dec, &stride);
    float s = x[(size_t)b * stride + i] + fc1b[i];
    #pragma unroll
    for (int p = 0; p < 8; p++) s += g_part[(size_t)p * NB * NI + idx];
    g_out[(size_t)t * NB * NI + idx] = s;
}

// logit[b] = sigmoid( sum_{t,i} out[t][b][i] * fc2_w[t*NI+i] + fc2_b )
__global__ void k_final(const float* __restrict__ fc2w, const float* __restrict__ fc2b,
                        float* __restrict__ y) {
    int b = blockIdx.x;
    float s = 0.0f;
    for (int f = threadIdx.x; f < NT * NI; f += 256) {
        int t = f / NI;
        int i = f - t * NI;
        s += g_out[(size_t)t * NB * NI + (size_t)b * NI + i] * fc2w[f];
    }
    __shared__ float red[256];
    red[threadIdx.x] = s;
    __syncthreads();
    for (int off = 128; off > 0; off >>= 1) {
        if (threadIdx.x < off) red[threadIdx.x] += red[threadIdx.x + off];
        __syncthreads();
    }
    if (threadIdx.x == 0)
        y[b] = 1.0f / (1.0f + expf(-(red[0] + fc2b[0])));
}

extern "C" void kernel_launch(void* const* d_in, const int* in_sizes, int n_in,
                              void* d_out, int out_size) {
    const float* enc  = (const float*)d_in[0];
    const float* dec  = (const float*)d_in[1];
    const float* w_ih = (const float*)d_in[2];
    const float* w_hh = (const float*)d_in[3];
    const float* b_ih = (const float*)d_in[4];
    const float* b_hh = (const float*)d_in[5];
    const float* fc1w = (const float*)d_in[6];
    const float* fc1b = (const float*)d_in[7];
    const float* fc2w = (const float*)d_in[8];
    const float* fc2b = (const float*)d_in[9];
    float* y = (float*)d_out;

    dim3 gemm_grid(48, 16);

    k_zero<<<(NB * NH + 255) / 256, 256>>>();

    // Encoding pass: GRU over all 74 frames
    for (int t = 0; t < NT; t++) {
        k_gi<<<gemm_grid, 256>>>(enc, dec, w_ih, b_ih, 0, t);
        k_gh<<<gemm_grid, 256>>>(w_hh);
        k_combine<<<(NB * NH) / 256, 256>>>(b_hh);
    }

    // Decode pass: autoregressive
    for (int t = 0; t < NT; t++) {
        int xkind = (t == 0) ? 0 : 1;
        int xt    = (t == 0) ? 0 : (t - 1);
        k_gi<<<gemm_grid, 256>>>(enc, dec, w_ih, b_ih, xkind, xt);
        k_gh<<<gemm_grid, 256>>>(w_hh);
        k_combine<<<(NB * NH) / 256, 256>>>(b_hh);
        k_out<<<dim3(16, 8), 256>>>(fc1w);
        k_outred<<<(NB * NI + 255) / 256, 256>>>(enc, dec, fc1b, xkind, xt, t);
    }

    k_final<<<NB, 256>>>(fc2w, fc2b, y);
}

// round 3
// speedup vs baseline: 2.6555x; 2.6555x over previous
#include <cuda_runtime.h>
#include <cuda_bf16.h>
#include <cstdint>
#include <math.h>

// ---------------- problem constants ----------------
constexpr int NB   = 1024;   // batch
constexpr int NH   = 1024;   // hidden
constexpr int NI   = 69;     // input feats
constexpr int NSRC = 50;
constexpr int NDEC = 24;
constexpr int NT   = 74;     // frames
constexpr int KX   = 128;    // padded x width
constexpr int KA   = NH + KX;        // 1152 augmented K
constexpr int NA   = 4 * NH;         // 4096 gate-interleaved N (n' = 4j+g)
constexpr int KC   = 64;             // K per chunk
constexpr int NCHUNK = KA / KC;      // 18
constexpr int NPASS  = 3;            // split-bf16 passes
constexpr int TOTCH  = NCHUNK * NPASS;   // 54

// smem: pipeline A[2]x16KB + B[2]x32KB = 96KB ; epilogue 128x264 fp32 = 132KB
constexpr int SMEM_BYTES = 128 * 264 * 4;   // 135168 (covers pipeline region)

// ---------------- device scratch ----------------
__device__ __align__(16) float          g_h32[2][NB * NH];
__device__ __align__(16) __nv_bfloat16  g_ahi[2][NB * KA];   // [b][k] aug: h | x
__device__ __align__(16) __nv_bfloat16  g_alo[2][NB * KA];
__device__ __align__(16) __nv_bfloat16  g_wBhi[KA * NA];     // [k][n'=4j+g]
__device__ __align__(16) __nv_bfloat16  g_wBlo[KA * NA];
__device__ __align__(16) float          g_x32[NB * KX];
__device__ __align__(16) float          g_outb[NT * NB * NI];
__device__ __align__(16) float          g_part[8 * NB * NI];

// ---------------- asm helpers (base PTX only) ----------------
__device__ __forceinline__ uint32_t smem_u32(const void* p) {
    uint32_t a;
    asm("{ .reg .u64 t; cvta.to.shared.u64 t, %1; cvt.u32.u64 %0, t; }" : "=r"(a) : "l"(p));
    return a;
}
__device__ __forceinline__ void cp16(uint32_t dst, const void* src) {
    asm volatile("cp.async.cg.shared.global [%0], [%1], 16;" :: "r"(dst), "l"(src));
}
__device__ __forceinline__ void cp_commit() {
    asm volatile("cp.async.commit_group;" ::: "memory");
}
__device__ __forceinline__ void ldsm4(uint32_t* r, uint32_t addr) {
    asm volatile("ldmatrix.sync.aligned.m8n8.x4.shared.b16 {%0,%1,%2,%3}, [%4];"
        : "=r"(r[0]), "=r"(r[1]), "=r"(r[2]), "=r"(r[3]) : "r"(addr));
}
__device__ __forceinline__ void ldsm4t(uint32_t* r, uint32_t addr) {
    asm volatile("ldmatrix.sync.aligned.m8n8.x4.trans.shared.b16 {%0,%1,%2,%3}, [%4];"
        : "=r"(r[0]), "=r"(r[1]), "=r"(r[2]), "=r"(r[3]) : "r"(addr));
}
__device__ __forceinline__ void mma16816(float* d, const uint32_t* a, const uint32_t* b) {
    asm volatile("mma.sync.aligned.m16n8k16.row.col.f32.bf16.bf16.f32 "
        "{%0,%1,%2,%3}, {%4,%5,%6,%7}, {%8,%9}, {%0,%1,%2,%3};"
        : "+f"(d[0]), "+f"(d[1]), "+f"(d[2]), "+f"(d[3])
        : "r"(a[0]), "r"(a[1]), "r"(a[2]), "r"(a[3]), "r"(b[0]), "r"(b[1]));
}

// ---------------- prep: gate-interleaved K-major split-bf16 weights ----------
// n' = 4j+g ; g0: r = [whh_r | wih_r], g1: z = [whh_z | wih_z],
// g2: i_n = [0 | wih_n], g3: h_n = [whh_n | 0]
__global__ void k_prep(const float* __restrict__ w_ih, const float* __restrict__ w_hh) {
    size_t idx = (size_t)blockIdx.x * blockDim.x + threadIdx.x;
    if (idx >= (size_t)KA * NA) return;
    int k  = (int)(idx / NA);
    int np = (int)(idx % NA);
    int j = np >> 2, g = np & 3;
    float v = 0.0f;
    if (g == 0) {
        if (k < NH) v = w_hh[(size_t)j * NH + k];
        else if (k - NH < NI) v = w_ih[(size_t)j * NI + (k - NH)];
    } else if (g == 1) {
        if (k < NH) v = w_hh[(size_t)(NH + j) * NH + k];
        else if (k - NH < NI) v = w_ih[(size_t)(NH + j) * NI + (k - NH)];
    } else if (g == 2) {
        if (k >= NH && k - NH < NI) v = w_ih[(size_t)(2 * NH + j) * NI + (k - NH)];
    } else {
        if (k < NH) v = w_hh[(size_t)(2 * NH + j) * NH + k];
    }
    __nv_bfloat16 hi = __float2bfloat16(v);
    g_wBhi[idx] = hi;
    g_wBlo[idx] = __float2bfloat16(v - __bfloat162float(hi));
}

__global__ void k_init() {
    int idx = blockIdx.x * blockDim.x + threadIdx.x;
    if (idx < NB * KA) {
        g_ahi[0][idx] = __float2bfloat16(0.0f);
        g_alo[0][idx] = __float2bfloat16(0.0f);
        g_ahi[1][idx] = __float2bfloat16(0.0f);
        g_alo[1][idx] = __float2bfloat16(0.0f);
    }
    if (idx < NB * NH) g_h32[0][idx] = 0.0f;
}

// set x part of aug buffer `buf` (and residual g_x32) from a frame
__global__ void k_setx(const float* __restrict__ src, int stride, int buf) {
    int idx = blockIdx.x * blockDim.x + threadIdx.x;
    if (idx >= NB * KX) return;
    int b = idx >> 7, c = idx & (KX - 1);
    float v = (c < NI) ? src[(size_t)b * stride + c] : 0.0f;
    g_x32[idx] = v;
    __nv_bfloat16 hi = __float2bfloat16(v);
    size_t off = (size_t)b * KA + NH + c;
    g_ahi[buf][off] = hi;
    g_alo[buf][off] = __float2bfloat16(v - __bfloat162float(hi));
}

// ---------------- fused GRU step: HMMA GEMM + gate epilogue ------------------
// grid (16 n-tiles x 8 m-tiles), 256 threads (8 warps, warp tile 64x64)
__global__ void __launch_bounds__(256, 1)
k_gru(int cur, const float* __restrict__ bih, const float* __restrict__ bhh) {
    extern __shared__ char sm[];
    const uint32_t sb = smem_u32(sm);
    const int tid = threadIdx.x;
    const int wid = tid >> 5, l = tid & 31;
    const int wm = wid >> 2, wn = wid & 3;      // warp grid 2(m) x 4(n)
    const int m0 = blockIdx.y * 128;
    const int n0 = blockIdx.x * 256;
    const int j0 = blockIdx.x * 64;
    const int nxt = cur ^ 1;

    const __nv_bfloat16* Ahi = g_ahi[cur];
    const __nv_bfloat16* Alo = g_alo[cur];

    float d[4][8][4] = {};   // [mt 16-row][nb 8-col][frag]

    auto load_chunk = [&](int c) {
        const int p = c / NCHUNK, kc = c % NCHUNK;
        const int buf = c & 1;
        const __nv_bfloat16* As = (p < 2) ? Ahi : Alo;
        const __nv_bfloat16* Bs = (p == 1) ? g_wBlo : g_wBhi;
        const uint32_t abase = sb + buf * 16384;
        const uint32_t bbase = sb + 32768 + buf * 32768;
        #pragma unroll
        for (int i = 0; i < 4; i++) {             // A: 128x64 bf16, 1024 granules
            int v = tid + i * 256;
            int m = v >> 3, kg = v & 7;
            cp16(abase + m * 128 + ((kg ^ (m & 7)) << 4),
                 As + (size_t)(m0 + m) * KA + kc * 64 + kg * 8);
        }
        #pragma unroll
        for (int i = 0; i < 8; i++) {             // B: 64x256 bf16, 2048 granules
            int v = tid + i * 256;
            int k = v >> 5, ng = v & 31;
            cp16(bbase + k * 512 + ((ng ^ (k & 7)) << 4),
                 Bs + (size_t)(kc * 64 + k) * NA + n0 + ng * 8);
        }
        cp_commit();
    };

    load_chunk(0);
    for (int c = 0; c < TOTCH; c++) {
        if (c + 1 < TOTCH) {
            load_chunk(c + 1);
            asm volatile("cp.async.wait_group 1;" ::: "memory");
        } else {
            asm volatile("cp.async.wait_group 0;" ::: "memory");
        }
        __syncthreads();
        const int buf = c & 1;
        const uint32_t abase = sb + buf * 16384 + wm * 64 * 128;
        const uint32_t bbase = sb + 32768 + buf * 32768;
        #pragma unroll
        for (int kk = 0; kk < 4; kk++) {
            uint32_t a[4][4], b[4][4];
            #pragma unroll
            for (int mt = 0; mt < 4; mt++) {
                int m = mt * 16 + (l & 15);
                int kg = kk * 2 + (l >> 4);
                ldsm4(a[mt], abase + m * 128 + ((kg ^ (m & 7)) << 4));
            }
            #pragma unroll
            for (int nq = 0; nq < 4; nq++) {      // each covers 16 n'
                int k = kk * 16 + (l & 15);
                int ng = wn * 8 + nq * 2 + (l >> 4);
                ldsm4t(b[nq], bbase + k * 512 + ((ng ^ (k & 7)) << 4));
            }
            #pragma unroll
            for (int mt = 0; mt < 4; mt++)
                #pragma unroll
                for (int nb = 0; nb < 8; nb++)
                    mma16816(d[mt][nb], a[mt], b[nb >> 1] + (nb & 1) * 2);
        }
        __syncthreads();   // before next load overwrites this buffer
    }

    // ---- epilogue: fragments -> smem -> gates -> h_new ----
    float* sC = (float*)sm;   // [128][264]
    #pragma unroll
    for (int mt = 0; mt < 4; mt++) {
        int r = wm * 64 + mt * 16 + (l >> 2);
        #pragma unroll
        for (int nb = 0; nb < 8; nb++) {
            int cc = wn * 64 + nb * 8 + (l & 3) * 2;
            sC[r * 264 + cc]           = d[mt][nb][0];
            sC[r * 264 + cc + 1]       = d[mt][nb][1];
            sC[(r + 8) * 264 + cc]     = d[mt][nb][2];
            sC[(r + 8) * 264 + cc + 1] = d[mt][nb][3];
        }
    }
    __syncthreads();

    #pragma unroll
    for (int i = 0; i < 32; i++) {
        int idx = i * 256 + tid;
        int m = idx >> 6, j = idx & 63;
        int jg = j0 + j;
        float4 q = *(const float4*)&sC[m * 264 + 4 * j];   // r, z, i_n, h_n
        float br  = __ldg(&bih[jg]) + __ldg(&bhh[jg]);
        float bz  = __ldg(&bih[NH + jg]) + __ldg(&bhh[NH + jg]);
        float bin = __ldg(&bih[2 * NH + jg]);
        float bhn = __ldg(&bhh[2 * NH + jg]);
        float r = 1.0f / (1.0f + expf(-(q.x + br)));
        float z = 1.0f / (1.0f + expf(-(q.y + bz)));
        float n = tanhf(q.z + bin + r * (q.w + bhn));
        float hold = g_h32[cur][(size_t)(m0 + m) * NH + jg];
        float hnew = (1.0f - z) * n + z * hold;
        g_h32[nxt][(size_t)(m0 + m) * NH + jg] = hnew;
        __nv_bfloat16 hi = __float2bfloat16(hnew);
        size_t off = (size_t)(m0 + m) * KA + jg;
        g_ahi[nxt][off] = hi;
        g_alo[nxt][off] = __float2bfloat16(hnew - __bfloat162float(hi));
    }
}

// ---------------- decode fc1: split-K partials (fp32 SIMT) ----------------
__global__ void k_out(const float* __restrict__ fc1w, int p) {
    __shared__ float As[32][68];
    __shared__ float Bs[32][80];
    const float* hh = g_h32[p];
    const int m0 = blockIdx.x * 64;
    const int ks = blockIdx.y;
    const int tid = threadIdx.x;
    const int tx = tid & 15, ty = tid >> 4;
    float acc[4][5] = {};
    for (int kt = 0; kt < 4; kt++) {
        int k0 = ks * 128 + kt * 32;
        #pragma unroll
        for (int u = 0; u < 2; u++) {
            int idx = tid + u * 256;
            int m = idx >> 3;
            int kq = (idx & 7) * 4;
            float4 va = *(const float4*)(hh + (size_t)(m0 + m) * NH + k0 + kq);
            As[kq + 0][m] = va.x; As[kq + 1][m] = va.y;
            As[kq + 2][m] = va.z; As[kq + 3][m] = va.w;
        }
        for (int idx = tid; idx < 80 * 32; idx += 256) {
            int n = idx >> 5, k = idx & 31;
            Bs[k][n] = (n < NI) ? fc1w[(size_t)n * NH + k0 + k] : 0.0f;
        }
        __syncthreads();
        #pragma unroll
        for (int k = 0; k < 32; k++) {
            float4 a4 = *(const float4*)&As[k][ty * 4];
            float a[4] = {a4.x, a4.y, a4.z, a4.w};
            float bb[5];
            #pragma unroll
            for (int j = 0; j < 5; j++) bb[j] = Bs[k][tx * 5 + j];
            #pragma unroll
            for (int i = 0; i < 4; i++)
                #pragma unroll
                for (int j = 0; j < 5; j++)
                    acc[i][j] += a[i] * bb[j];
        }
        __syncthreads();
    }
    #pragma unroll
    for (int i = 0; i < 4; i++) {
        int m = m0 + ty * 4 + i;
        #pragma unroll
        for (int j = 0; j < 5; j++) {
            int n = tx * 5 + j;
            if (n < NI)
                g_part[(size_t)ks * NB * NI + (size_t)m * NI + n] = acc[i][j];
        }
    }
}

// out[t] = x + fc1_b + sum partials ; becomes next step's x (into buf nbuf)
__global__ void k_outred(const float* __restrict__ fc1b, int t, int nbuf) {
    int idx = blockIdx.x * blockDim.x + threadIdx.x;
    if (idx >= NB * NI) return;
    int b = idx / NI, i = idx - b * NI;
    float s = g_x32[(size_t)b * KX + i] + fc1b[i];
    #pragma unroll
    for (int p = 0; p < 8; p++) s += g_part[(size_t)p * NB * NI + idx];
    g_outb[(size_t)t * NB * NI + idx] = s;
    g_x32[(size_t)b * KX + i] = s;
    __nv_bfloat16 hi = __float2bfloat16(s);
    size_t off = (size_t)b * KA + NH + i;
    g_ahi[nbuf][off] = hi;
    g_alo[nbuf][off] = __float2bfloat16(s - __bfloat162float(hi));
}

__global__ void k_final(const float* __restrict__ fc2w, const float* __restrict__ fc2b,
                        float* __restrict__ y) {
    int b = blockIdx.x;
    float s = 0.0f;
    for (int f = threadIdx.x; f < NT * NI; f += 256) {
        int t = f / NI, i = f - t * NI;
        s += g_outb[(size_t)t * NB * NI + (size_t)b * NI + i] * fc2w[f];
    }
    __shared__ float red[256];
    red[threadIdx.x] = s;
    __syncthreads();
    for (int off = 128; off > 0; off >>= 1) {
        if (threadIdx.x < off) red[threadIdx.x] += red[threadIdx.x + off];
        __syncthreads();
    }
    if (threadIdx.x == 0)
        y[b] = 1.0f / (1.0f + expf(-(red[0] + fc2b[0])));
}

// ---------------- launch ----------------
extern "C" void kernel_launch(void* const* d_in, const int* in_sizes, int n_in,
                              void* d_out, int out_size) {
    const float* enc  = (const float*)d_in[0];
    const float* dec  = (const float*)d_in[1];
    const float* w_ih = (const float*)d_in[2];
    const float* w_hh = (const float*)d_in[3];
    const float* b_ih = (const float*)d_in[4];
    const float* b_hh = (const float*)d_in[5];
    const float* fc1w = (const float*)d_in[6];
    const float* fc1b = (const float*)d_in[7];
    const float* fc2w = (const float*)d_in[8];
    const float* fc2b = (const float*)d_in[9];
    float* y = (float*)d_out;

    cudaFuncSetAttribute(k_gru, cudaFuncAttributeMaxDynamicSharedMemorySize, SMEM_BYTES);

    k_prep<<<((int)((size_t)KA * NA) + 255) / 256, 256>>>(w_ih, w_hh);
    k_init<<<(NB * KA + 255) / 256, 256>>>();

    int cur = 0;
    for (int s = 0; s < 2 * NT; ++s) {
        if (s <= NT) {
            int f = (s == NT) ? 0 : s;
            const float* src;
            int stride;
            if (f < NSRC) { src = enc + (size_t)f * NI; stride = NSRC * NI; }
            else          { src = dec + (size_t)(f - NSRC) * NI; stride = NDEC * NI; }
            k_setx<<<(NB * KX + 255) / 256, 256>>>(src, stride, cur);
        }
        k_gru<<<dim3(16, 8), 256, SMEM_BYTES>>>(cur, b_ih, b_hh);
        if (s >= NT) {
            k_out<<<dim3(16, 8), 256>>>(fc1w, cur ^ 1);
            k_outred<<<(NB * NI + 255) / 256, 256>>>(fc1b, s - NT, cur ^ 1);
        }
        cur ^= 1;
    }
    k_final<<<NB, 256>>>(fc2w, fc2b, y);
}

// round 4
// speedup vs baseline: 4.8723x; 1.8348x over previous
#include <cuda_runtime.h>
#include <cuda_fp16.h>
#include <cstdint>
#include <math.h>

// ---------------- problem constants ----------------
constexpr int NB   = 1024;
constexpr int NH   = 1024;
constexpr int NI   = 69;
constexpr int NSRC = 50;
constexpr int NDEC = 24;
constexpr int NT   = 74;
constexpr int KX   = 128;
constexpr int KA   = NH + KX;     // 1152
constexpr int NCHUNK = KA / 64;   // 18

constexpr int STAGE = 65536;      // A 16KB + B 6x8KB = 64KB
constexpr int SMEM_BYTES = 128 * 260 * 4;  // 133120 (>= 2*STAGE)

// ---------------- device scratch ----------------
__device__ __align__(16) float  g_h32[2][NB * NH];
__device__ __align__(16) __half g_ah[2][NB * KA];      // fp16 aug activations [b][k]
__device__ __align__(16) __half g_wBhi[4 * KA * NH];   // [g][k][j]
__device__ __align__(16) __half g_wBlo[4 * KA * NH];
__device__ __align__(16) float  g_x32[NB * KX];
__device__ __align__(16) float  g_outb[NT * NB * NI];
__device__ __align__(16) float  g_part[8 * NB * NI];

// ---------------- asm helpers (base PTX only) ----------------
__device__ __forceinline__ uint32_t smem_u32(const void* p) {
    uint32_t a;
    asm("{ .reg .u64 t; cvta.to.shared.u64 t, %1; cvt.u32.u64 %0, t; }" : "=r"(a) : "l"(p));
    return a;
}
__device__ __forceinline__ void cp16(uint32_t dst, const void* src) {
    asm volatile("cp.async.cg.shared.global [%0], [%1], 16;" :: "r"(dst), "l"(src));
}
__device__ __forceinline__ void cp_commit() {
    asm volatile("cp.async.commit_group;" ::: "memory");
}
__device__ __forceinline__ void ldsm4(uint32_t* r, uint32_t addr) {
    asm volatile("ldmatrix.sync.aligned.m8n8.x4.shared.b16 {%0,%1,%2,%3}, [%4];"
        : "=r"(r[0]), "=r"(r[1]), "=r"(r[2]), "=r"(r[3]) : "r"(addr));
}
__device__ __forceinline__ void ldsm4t(uint32_t* r, uint32_t addr) {
    asm volatile("ldmatrix.sync.aligned.m8n8.x4.trans.shared.b16 {%0,%1,%2,%3}, [%4];"
        : "=r"(r[0]), "=r"(r[1]), "=r"(r[2]), "=r"(r[3]) : "r"(addr));
}
__device__ __forceinline__ void mma16816(float* d, const uint32_t* a, const uint32_t* b) {
    asm volatile("mma.sync.aligned.m16n8k16.row.col.f32.f16.f16.f32 "
        "{%0,%1,%2,%3}, {%4,%5,%6,%7}, {%8,%9}, {%0,%1,%2,%3};"
        : "+f"(d[0]), "+f"(d[1]), "+f"(d[2]), "+f"(d[3])
        : "r"(a[0]), "r"(a[1]), "r"(a[2]), "r"(a[3]), "r"(b[0]), "r"(b[1]));
}

// ---------------- prep: per-gate K-major split-fp16 weights ----------------
// [g][k][j]: g0 r = [whh_r|wih_r], g1 z = [whh_z|wih_z],
//            g2 i_n = [0|wih_n],  g3 h_n = [whh_n|0]
__global__ void k_prep(const float* __restrict__ w_ih, const float* __restrict__ w_hh) {
    size_t idx = (size_t)blockIdx.x * blockDim.x + threadIdx.x;
    if (idx >= (size_t)4 * KA * NH) return;
    int j = (int)(idx % NH);
    int t = (int)(idx / NH);
    int k = t % KA;
    int g = t / KA;
    float v = 0.0f;
    if (g == 0) {
        if (k < NH) v = w_hh[(size_t)j * NH + k];
        else if (k - NH < NI) v = w_ih[(size_t)j * NI + (k - NH)];
    } else if (g == 1) {
        if (k < NH) v = w_hh[(size_t)(NH + j) * NH + k];
        else if (k - NH < NI) v = w_ih[(size_t)(NH + j) * NI + (k - NH)];
    } else if (g == 2) {
        if (k >= NH && k - NH < NI) v = w_ih[(size_t)(2 * NH + j) * NI + (k - NH)];
    } else {
        if (k < NH) v = w_hh[(size_t)(2 * NH + j) * NH + k];
    }
    __half hi = __float2half(v);
    g_wBhi[idx] = hi;
    g_wBlo[idx] = __float2half(v - __half2float(hi));
}

__global__ void k_init() {
    int idx = blockIdx.x * blockDim.x + threadIdx.x;
    if (idx < NB * KA) {
        g_ah[0][idx] = __float2half(0.0f);
        g_ah[1][idx] = __float2half(0.0f);
    }
    if (idx < NB * NH) g_h32[0][idx] = 0.0f;
}

__global__ void k_setx(const float* __restrict__ src, int stride, int buf) {
    int idx = blockIdx.x * blockDim.x + threadIdx.x;
    if (idx >= NB * KX) return;
    int b = idx >> 7, c = idx & (KX - 1);
    float v = (c < NI) ? src[(size_t)b * stride + c] : 0.0f;
    g_x32[idx] = v;
    g_ah[buf][(size_t)b * KA + NH + c] = __float2half(v);
}

// ---------------- fused GRU step ----------------
// grid (16 j-tiles, 8 m-tiles), 512 threads (16 warps, warp tile 32m x 64n).
// warp wn in 0..3 owns gate wn; gate 2 active only for x-chunks (c>=16),
// gate 3 only for h-chunks (c<16).
__global__ void __launch_bounds__(512, 1)
k_gru(int cur, const float* __restrict__ bih, const float* __restrict__ bhh) {
    extern __shared__ char sm[];
    const uint32_t sb = smem_u32(sm);
    const int tid = threadIdx.x;
    const int wid = tid >> 5, l = tid & 31;
    const int wm = wid & 3, wn = wid >> 2;
    const int m0 = blockIdx.y * 128;
    const int j0 = blockIdx.x * 64;
    const int nxt = cur ^ 1;

    const __half* A = g_ah[cur];

    float d[2][8][4] = {};

    auto load_chunk = [&](int c) {
        const int buf = c & 1;
        const uint32_t st = sb + buf * STAGE;
        // A: 128 x 64 fp16 = 1024 granules
        #pragma unroll
        for (int i = 0; i < 2; i++) {
            int v = tid + i * 512;
            int m = v >> 3, kg = v & 7;
            cp16(st + m * 128 + ((kg ^ (m & 7)) << 4),
                 A + (size_t)(m0 + m) * KA + c * 64 + kg * 8);
        }
        // B: 6 tiles (2 passes x 3 slots) of 64k x 64j fp16 = 3072 granules
        #pragma unroll
        for (int i = 0; i < 6; i++) {
            int v = tid + i * 512;
            int tb = v >> 9;                 // 0..5
            int p = (tb >= 3), s = tb - p * 3;
            int r = (v >> 3) & 63, cg = v & 7;
            int g = (s < 2) ? s : ((c < 16) ? 3 : 2);
            const __half* W = p ? g_wBlo : g_wBhi;
            cp16(st + 16384 + tb * 8192 + r * 128 + ((cg ^ (r & 7)) << 4),
                 W + ((size_t)g * KA + c * 64 + r) * NH + j0 + cg * 8);
        }
        cp_commit();
    };

    const bool act_h = (wn < 2) || (wn == 3);   // active for c < 16
    const bool act_x = (wn < 2) || (wn == 2);   // active for c >= 16
    const int slot = (wn < 2) ? wn : 2;

    load_chunk(0);
    for (int c = 0; c < NCHUNK; c++) {
        if (c + 1 < NCHUNK) {
            load_chunk(c + 1);
            asm volatile("cp.async.wait_group 1;" ::: "memory");
        } else {
            asm volatile("cp.async.wait_group 0;" ::: "memory");
        }
        __syncthreads();
        const bool active = (c < 16) ? act_h : act_x;
        if (active) {
            const uint32_t st = sb + (c & 1) * STAGE;
            const uint32_t abase = st + wm * 32 * 128;
            #pragma unroll
            for (int kk = 0; kk < 4; kk++) {
                uint32_t a[2][4];
                #pragma unroll
                for (int mt = 0; mt < 2; mt++) {
                    int m = mt * 16 + (l & 15);
                    int kg = kk * 2 + (l >> 4);
                    ldsm4(a[mt], abase + m * 128 + ((kg ^ ((m + wm * 32) & 7)) << 4));
                }
                #pragma unroll
                for (int p = 0; p < 2; p++) {
                    const uint32_t bbase = st + 16384 + (p * 3 + slot) * 8192;
                    uint32_t b[4][4];
                    #pragma unroll
                    for (int nq = 0; nq < 4; nq++) {
                        int k = kk * 16 + (l & 15);
                        int ng = nq * 2 + (l >> 4);
                        ldsm4t(b[nq], bbase + k * 128 + ((ng ^ (k & 7)) << 4));
                    }
                    #pragma unroll
                    for (int mt = 0; mt < 2; mt++)
                        #pragma unroll
                        for (int nb = 0; nb < 8; nb++)
                            mma16816(d[mt][nb], a[mt], b[nb >> 1] + (nb & 1) * 2);
                }
            }
        }
        __syncthreads();
    }

    // ---- epilogue ----
    float* sC = (float*)sm;   // [128][260]
    #pragma unroll
    for (int mt = 0; mt < 2; mt++) {
        int r = wm * 32 + mt * 16 + (l >> 2);
        #pragma unroll
        for (int nb = 0; nb < 8; nb++) {
            int cc = wn * 64 + nb * 8 + (l & 3) * 2;
            *(float2*)&sC[r * 260 + cc]       = make_float2(d[mt][nb][0], d[mt][nb][1]);
            *(float2*)&sC[(r + 8) * 260 + cc] = make_float2(d[mt][nb][2], d[mt][nb][3]);
        }
    }
    __syncthreads();

    #pragma unroll
    for (int i = 0; i < 16; i++) {
        int idx = i * 512 + tid;
        int m = idx >> 6, j = idx & 63;
        int jg = j0 + j;
        float rc = sC[m * 260 + j];
        float zc = sC[m * 260 + 64 + j];
        float ic = sC[m * 260 + 128 + j];
        float hc = sC[m * 260 + 192 + j];
        float br  = __ldg(&bih[jg]) + __ldg(&bhh[jg]);
        float bz  = __ldg(&bih[NH + jg]) + __ldg(&bhh[NH + jg]);
        float bin = __ldg(&bih[2 * NH + jg]);
        float bhn = __ldg(&bhh[2 * NH + jg]);
        float r = 1.0f / (1.0f + expf(-(rc + br)));
        float z = 1.0f / (1.0f + expf(-(zc + bz)));
        float n = tanhf(ic + bin + r * (hc + bhn));
        float hold = g_h32[cur][(size_t)(m0 + m) * NH + jg];
        float hnew = (1.0f - z) * n + z * hold;
        g_h32[nxt][(size_t)(m0 + m) * NH + jg] = hnew;
        g_ah[nxt][(size_t)(m0 + m) * KA + jg] = __float2half(hnew);
    }
}

// ---------------- decode fc1: split-K partials (fp32 SIMT) ----------------
__global__ void k_out(const float* __restrict__ fc1w, int p) {
    __shared__ float As[32][68];
    __shared__ float Bs[32][80];
    const float* hh = g_h32[p];
    const int m0 = blockIdx.x * 64;
    const int ks = blockIdx.y;
    const int tid = threadIdx.x;
    const int tx = tid & 15, ty = tid >> 4;
    float acc[4][5] = {};
    for (int kt = 0; kt < 4; kt++) {
        int k0 = ks * 128 + kt * 32;
        #pragma unroll
        for (int u = 0; u < 2; u++) {
            int idx = tid + u * 256;
            int m = idx >> 3;
            int kq = (idx & 7) * 4;
            float4 va = *(const float4*)(hh + (size_t)(m0 + m) * NH + k0 + kq);
            As[kq + 0][m] = va.x; As[kq + 1][m] = va.y;
            As[kq + 2][m] = va.z; As[kq + 3][m] = va.w;
        }
        for (int idx = tid; idx < 80 * 32; idx += 256) {
            int n = idx >> 5, k = idx & 31;
            Bs[k][n] = (n < NI) ? fc1w[(size_t)n * NH + k0 + k] : 0.0f;
        }
        __syncthreads();
        #pragma unroll
        for (int k = 0; k < 32; k++) {
            float4 a4 = *(const float4*)&As[k][ty * 4];
            float a[4] = {a4.x, a4.y, a4.z, a4.w};
            float bb[5];
            #pragma unroll
            for (int j = 0; j < 5; j++) bb[j] = Bs[k][tx * 5 + j];
            #pragma unroll
            for (int i = 0; i < 4; i++)
                #pragma unroll
                for (int j = 0; j < 5; j++)
                    acc[i][j] += a[i] * bb[j];
        }
        __syncthreads();
    }
    #pragma unroll
    for (int i = 0; i < 4; i++) {
        int m = m0 + ty * 4 + i;
        #pragma unroll
        for (int j = 0; j < 5; j++) {
            int n = tx * 5 + j;
            if (n < NI)
                g_part[(size_t)ks * NB * NI + (size_t)m * NI + n] = acc[i][j];
        }
    }
}

__global__ void k_outred(const float* __restrict__ fc1b, int t, int nbuf) {
    int idx = blockIdx.x * blockDim.x + threadIdx.x;
    if (idx >= NB * NI) return;
    int b = idx / NI, i = idx - b * NI;
    float s = g_x32[(size_t)b * KX + i] + fc1b[i];
    #pragma unroll
    for (int p = 0; p < 8; p++) s += g_part[(size_t)p * NB * NI + idx];
    g_outb[(size_t)t * NB * NI + idx] = s;
    g_x32[(size_t)b * KX + i] = s;
    g_ah[nbuf][(size_t)b * KA + NH + i] = __float2half(s);
}

__global__ void k_final(const float* __restrict__ fc2w, const float* __restrict__ fc2b,
                        float* __restrict__ y) {
    int b = blockIdx.x;
    float s = 0.0f;
    for (int f = threadIdx.x; f < NT * NI; f += 256) {
        int t = f / NI, i = f - t * NI;
        s += g_outb[(size_t)t * NB * NI + (size_t)b * NI + i] * fc2w[f];
    }
    __shared__ float red[256];
    red[threadIdx.x] = s;
    __syncthreads();
    for (int off = 128; off > 0; off >>= 1) {
        if (threadIdx.x < off) red[threadIdx.x] += red[threadIdx.x + off];
        __syncthreads();
    }
    if (threadIdx.x == 0)
        y[b] = 1.0f / (1.0f + expf(-(red[0] + fc2b[0])));
}

// ---------------- launch ----------------
extern "C" void kernel_launch(void* const* d_in, const int* in_sizes, int n_in,
                              void* d_out, int out_size) {
    const float* enc  = (const float*)d_in[0];
    const float* dec  = (const float*)d_in[1];
    const float* w_ih = (const float*)d_in[2];
    const float* w_hh = (const float*)d_in[3];
    const float* b_ih = (const float*)d_in[4];
    const float* b_hh = (const float*)d_in[5];
    const float* fc1w = (const float*)d_in[6];
    const float* fc1b = (const float*)d_in[7];
    const float* fc2w = (const float*)d_in[8];
    const float* fc2b = (const float*)d_in[9];
    float* y = (float*)d_out;

    cudaFuncSetAttribute(k_gru, cudaFuncAttributeMaxDynamicSharedMemorySize, SMEM_BYTES);

    k_prep<<<(int)(((size_t)4 * KA * NH + 255) / 256), 256>>>(w_ih, w_hh);
    k_init<<<(NB * KA + 255) / 256, 256>>>();

    int cur = 0;
    for (int s = 0; s < 2 * NT; ++s) {
        if (s <= NT) {
            int f = (s == NT) ? 0 : s;
            const float* src;
            int stride;
            if (f < NSRC) { src = enc + (size_t)f * NI; stride = NSRC * NI; }
            else          { src = dec + (size_t)(f - NSRC) * NI; stride = NDEC * NI; }
            k_setx<<<(NB * KX + 255) / 256, 256>>>(src, stride, cur);
        }
        k_gru<<<dim3(16, 8), 512, SMEM_BYTES>>>(cur, b_ih, b_hh);
        if (s >= NT) {
            k_out<<<dim3(16, 8), 256>>>(fc1w, cur ^ 1);
            k_outred<<<(NB * NI + 255) / 256, 256>>>(fc1b, s - NT, cur ^ 1);
        }
        cur ^= 1;
    }
    k_final<<<NB, 256>>>(fc2w, fc2b, y);
}